// round 15
// baseline (speedup 1.0000x reference)
#include <cuda_runtime.h>

// Hausdorff distance, batched N=8, grid 96x96, coords (i/96, j/96).
// haus[s] = max(directed(A\B -> B), directed(B\A -> A)), out = mean over s.
// Single fused pass: warp w owns rows 3w..3w+2, lane owns j = lane,+32,+64.
// dir eliminated via pointer swap (X=src-side, Y=tgt-side).
// Row masks via 9 ballots; rd2 via 32-bit centered window (funnelshift+clz/ffs),
// exact 96-bit fallback behind a per-row-triple warp vote; one barrier;
// column scan: branchless di=1 probe + early-exit loop. Empty-target detected
// from the sentinel value (m>=40000), no separate reduction needed.

#define HD 96
#define WD 96
#define HW (HD * WD)
#define NT 1024

__device__ float        g_dir[64];     // [s*2 + dir]
__device__ unsigned int g_count = 0;   // self-resetting last-block counter

// Exact left/right nearest-set-bit distance in a 96-bit row (cold path only).
static __device__ __noinline__ int exact_dl(int j, unsigned m0, unsigned m1, unsigned m2) {
    unsigned long long lo = (unsigned long long)m0 | ((unsigned long long)m1 << 32);
    if (j < 64) {
        unsigned long long x = lo & (~0ULL >> (63 - j));
        return x ? (j - (63 - __clzll(x))) : 200;
    } else {
        unsigned x = m2 & (~0u >> (95 - j));
        if (x)  return j - (64 + 31 - __clz(x));
        if (lo) return j - (63 - __clzll(lo));
        return 200;
    }
}
static __device__ __noinline__ int exact_dr(int j, unsigned m0, unsigned m1, unsigned m2) {
    unsigned long long lo = (unsigned long long)m0 | ((unsigned long long)m1 << 32);
    if (j < 64) {
        unsigned long long y = lo >> j;
        if (y)  return __ffsll(y) - 1;
        if (m2) return (64 - j) + __ffs(m2) - 1;
        return 200;
    } else {
        unsigned y = m2 >> (j - 64);
        return y ? (__ffs(y) - 1) : 200;
    }
}

__global__ void __launch_bounds__(NT) hausdorff_kernel(
    const float* __restrict__ pred, const float* __restrict__ targ,
    float* __restrict__ out, int n) {
    __shared__ unsigned short s_rd2[HW];   // squared row distance (sentinel 40000)
    __shared__ int s_red[32];

    const int s    = blockIdx.x;
    const int dir  = blockIdx.y;           // 0: src=A\B tgt=B ; 1: src=B\A tgt=A
    const int tid  = threadIdx.x;
    const int lane = tid & 31;
    const int wrp  = tid >> 5;             // 0..31 -> rows 3w..3w+2

    // Pointer swap makes the rest of the kernel direction-free:
    // directed(X\Y -> Y) with (X,Y) = dir ? (targ,pred) : (pred,targ).
    const float* __restrict__ X = dir ? (targ + s * HW) : (pred + s * HW);
    const float* __restrict__ Y = dir ? (pred + s * HW) : (targ + s * HW);

    // ---- Load this warp's 3 rows (both arrays), 18 coalesced scalar loads.
    float xv[9], yv[9];
    #pragma unroll
    for (int rr = 0; rr < 3; rr++) {
        const int base = (wrp * 3 + rr) * WD + lane;
        #pragma unroll
        for (int c = 0; c < 3; c++) {
            xv[rr * 3 + c] = X[base + 32 * c];
            yv[rr * 3 + c] = Y[base + 32 * c];
        }
    }

    // ---- Target masks via 9 ballots; source bits per-lane; rd2 per slot.
    unsigned srcbits = 0;            // bit rr*3+c: this lane's pixel is a source
    int rd2own[9];
    const bool loHalf = (lane < 16);
    #pragma unroll
    for (int rr = 0; rr < 3; rr++) {
        unsigned tm[3];
        #pragma unroll
        for (int c = 0; c < 3; c++) {
            bool t = yv[rr * 3 + c] > 0.5f;   // round(v)>0.5 <=> v>0.5 on [0,1)
            bool src = (xv[rr * 3 + c] > 0.5f) && !t;
            tm[c] = __ballot_sync(0xffffffffu, t);
            srcbits |= (unsigned)src << (rr * 3 + c);
        }
        const int i = wrp * 3 + rr;

        unsigned xw[3], yw[3];
        int dl[3], dr[3];
        unsigned emptyAny = 0;
        #pragma unroll
        for (int c = 0; c < 3; c++) {
            const unsigned mprev = (c == 0) ? 0u : tm[c - 1];
            const unsigned mcur  = tm[c];
            const unsigned mnext = (c == 2) ? 0u : tm[c + 1];
            // 32-bit window: bit k <-> row position j-16+k, j = lane+32c
            unsigned w = loHalf ? __funnelshift_r(mprev, mcur, lane + 16)
                                : __funnelshift_r(mcur, mnext, lane - 16);
            xw[c] = w & 0x1FFFFu;      // positions j-16..j
            yw[c] = w >> 16;           // positions j..j+15
            dl[c] = __clz(xw[c]) - 15; // placeholder when empty
            dr[c] = __ffs(yw[c]) - 1;
            emptyAny |= (xw[c] == 0u) | (yw[c] == 0u);
        }
        // Cold path: ~P(5e-4) per warp-row-triple; exact on arbitrary inputs.
        if (__any_sync(0xffffffffu, emptyAny)) {
            #pragma unroll
            for (int c = 0; c < 3; c++) {
                const int j = lane + 32 * c;
                if (xw[c] == 0u) dl[c] = exact_dl(j, tm[0], tm[1], tm[2]);
                if (yw[c] == 0u) dr[c] = exact_dr(j, tm[0], tm[1], tm[2]);
            }
        }
        #pragma unroll
        for (int c = 0; c < 3; c++) {
            int v = min(dl[c], dr[c]);
            int v2 = v * v;
            rd2own[rr * 3 + c] = v2;
            s_rd2[i * WD + lane + 32 * c] = (unsigned short)v2;
        }
    }

    __syncthreads();   // makes s_rd2 visible block-wide

    // ---- Column scan: branchless di=1 probe + early-exit loop from di=2.
    // Clamped boundary probes only duplicate candidates already covered => min safe.
    int best = -1;
    #pragma unroll
    for (int c = 0; c < 3; c++) {
        const int j   = lane + 32 * c;
        const int loA = j;                 // row 0 clamp
        const int hiA = 95 * WD + j;       // row 95 clamp
        #pragma unroll
        for (int rr = 0; rr < 3; rr++) {
            const int idx = rr * 3 + c;
            const int i = wrp * 3 + rr;
            int bst = ((srcbits >> idx) & 1u) ? rd2own[idx] : -1;
            int au  = max(i * WD + j - WD, loA);
            int avd = min(i * WD + j + WD, hiA);
            bst = min(bst, 1 + (int)s_rd2[au]);
            bst = min(bst, 1 + (int)s_rd2[avd]);
            int di = 2, d2 = 4;
            while (d2 < bst) {             // rare: only when local rd2 > 4
                au  = max(au - WD, loA);
                avd = min(avd + WD, hiA);
                bst = min(bst, d2 + (int)s_rd2[au]);
                bst = min(bst, d2 + (int)s_rd2[avd]);
                d2 += 2 * di + 1;
                di++;
            }
            best = max(best, bst);
        }
    }

    // ---- Block max-reduction (REDUX within warps)
    best = __reduce_max_sync(0xffffffffu, best);
    if (lane == 0) s_red[wrp] = best;
    __syncthreads();
    if (wrp == 0) {
        int m = __reduce_max_sync(0xffffffffu, s_red[lane]);
        if (lane == 0) {
            // m == -1: empty source set -> 0
            // m >= 40000: source nonempty, target empty (sentinel rd2) -> 1e9
            // else: exact integer squared distance
            float r;
            if (m < 0)            r = 0.0f;
            else if (m >= 40000)  r = 1e9f;
            else                  r = sqrtf((float)m) * (1.0f / 96.0f);
            g_dir[s * 2 + dir] = r;
            __threadfence();
            unsigned int t = atomicAdd(&g_count, 1);
            if (t == (unsigned int)(2 * n - 1)) {    // last block: finish + reset
                __threadfence();
                volatile float* gd = g_dir;
                float acc = 0.0f;
                for (int i = 0; i < n; i++)
                    acc += fmaxf(gd[2 * i], gd[2 * i + 1]);
                out[0] = acc / (float)n;
                g_count = 0;                         // self-reset for next replay
            }
        }
    }
}

extern "C" void kernel_launch(void* const* d_in, const int* in_sizes, int n_in,
                              void* d_out, int out_size) {
    const float* pred = (const float*)d_in[0];
    const float* targ = (const float*)d_in[1];
    float* out = (float*)d_out;
    int n = in_sizes[0] / HW;   // batch size (8)

    dim3 grid(n, 2);
    hausdorff_kernel<<<grid, NT>>>(pred, targ, out, n);
}

// round 16
// speedup vs baseline: 1.0030x; 1.0030x over previous
#include <cuda_runtime.h>

// Hausdorff distance, batched N=8, grid 96x96, coords (i/96, j/96).
// haus[s] = max(directed(A\B -> B), directed(B\A -> A)), out = mean over s.
// Single fused pass: warp w owns rows 3w..3w+2, lane owns j = lane,+32,+64.
// dir eliminated via pointer swap. Row masks via 9 ballots; rd2 via 32-bit
// centered window (funnelshift+clz/ffs), exact fallback behind a warp vote;
// one barrier; column scan: di=1 probes mostly from registers, lazy rare tail.
// Empty target detected via sentinel (m>=40000). Lane-parallel finisher.

#define HD 96
#define WD 96
#define HW (HD * WD)
#define NT 1024

__device__ float        g_dir[64];     // [s*2 + dir]
__device__ unsigned int g_count = 0;   // self-resetting last-block counter

// Exact left/right nearest-set-bit distance in a 96-bit row (cold path only).
static __device__ __noinline__ int exact_dl(int j, unsigned m0, unsigned m1, unsigned m2) {
    unsigned long long lo = (unsigned long long)m0 | ((unsigned long long)m1 << 32);
    if (j < 64) {
        unsigned long long x = lo & (~0ULL >> (63 - j));
        return x ? (j - (63 - __clzll(x))) : 200;
    } else {
        unsigned x = m2 & (~0u >> (95 - j));
        if (x)  return j - (64 + 31 - __clz(x));
        if (lo) return j - (63 - __clzll(lo));
        return 200;
    }
}
static __device__ __noinline__ int exact_dr(int j, unsigned m0, unsigned m1, unsigned m2) {
    unsigned long long lo = (unsigned long long)m0 | ((unsigned long long)m1 << 32);
    if (j < 64) {
        unsigned long long y = lo >> j;
        if (y)  return __ffsll(y) - 1;
        if (m2) return (64 - j) + __ffs(m2) - 1;
        return 200;
    } else {
        unsigned y = m2 >> (j - 64);
        return y ? (__ffs(y) - 1) : 200;
    }
}

// Rare tail: outward probes from di=2 while d2 < b.
static __device__ __forceinline__ int tail_scan(const unsigned short* s_rd2,
                                                int i, int j, int b) {
    const int loA = j, hiA = 95 * WD + j;
    int au  = max(i - 1, 0) * WD + j;
    int avd = min(i + 1, HD - 1) * WD + j;
    int di = 2, d2 = 4;
    do {
        au  = max(au - WD, loA);
        avd = min(avd + WD, hiA);
        b = min(b, d2 + (int)s_rd2[au]);
        b = min(b, d2 + (int)s_rd2[avd]);
        d2 += 2 * di + 1;
        di++;
    } while (d2 < b);
    return b;
}

__global__ void __launch_bounds__(NT) hausdorff_kernel(
    const float* __restrict__ pred, const float* __restrict__ targ,
    float* __restrict__ out, int n) {
    __shared__ unsigned short s_rd2[HW];   // squared row distance (sentinel 40000)
    __shared__ int s_red[32];

    const int s    = blockIdx.x;
    const int dir  = blockIdx.y;           // 0: src=A\B tgt=B ; 1: src=B\A tgt=A
    const int tid  = threadIdx.x;
    const int lane = tid & 31;
    const int wrp  = tid >> 5;             // 0..31 -> rows 3w..3w+2

    // Pointer swap makes the rest of the kernel direction-free.
    const float* __restrict__ X = dir ? (targ + s * HW) : (pred + s * HW);
    const float* __restrict__ Y = dir ? (pred + s * HW) : (targ + s * HW);

    // ---- Load this warp's 3 rows (both arrays), 18 coalesced scalar loads.
    float xv[9], yv[9];
    #pragma unroll
    for (int rr = 0; rr < 3; rr++) {
        const int base = (wrp * 3 + rr) * WD + lane;
        #pragma unroll
        for (int c = 0; c < 3; c++) {
            xv[rr * 3 + c] = X[base + 32 * c];
            yv[rr * 3 + c] = Y[base + 32 * c];
        }
    }

    // ---- Target masks via 9 ballots; source bits per-lane; rd2 per slot.
    unsigned srcbits = 0;            // bit rr*3+c: this lane's pixel is a source
    int rd2own[9];
    const bool loHalf = (lane < 16);
    #pragma unroll
    for (int rr = 0; rr < 3; rr++) {
        unsigned tm[3];
        #pragma unroll
        for (int c = 0; c < 3; c++) {
            bool t = yv[rr * 3 + c] > 0.5f;   // round(v)>0.5 <=> v>0.5 on [0,1)
            bool src = (xv[rr * 3 + c] > 0.5f) && !t;
            tm[c] = __ballot_sync(0xffffffffu, t);
            srcbits |= (unsigned)src << (rr * 3 + c);
        }
        const int i = wrp * 3 + rr;

        unsigned xw[3], yw[3];
        int dl[3], dr[3];
        unsigned emptyAny = 0;
        #pragma unroll
        for (int c = 0; c < 3; c++) {
            const unsigned mprev = (c == 0) ? 0u : tm[c - 1];
            const unsigned mcur  = tm[c];
            const unsigned mnext = (c == 2) ? 0u : tm[c + 1];
            // 32-bit window: bit k <-> row position j-16+k, j = lane+32c
            unsigned w = loHalf ? __funnelshift_r(mprev, mcur, lane + 16)
                                : __funnelshift_r(mcur, mnext, lane - 16);
            xw[c] = w & 0x1FFFFu;      // positions j-16..j
            yw[c] = w >> 16;           // positions j..j+15
            dl[c] = __clz(xw[c]) - 15; // placeholder when empty
            dr[c] = __ffs(yw[c]) - 1;
            emptyAny |= (xw[c] == 0u) | (yw[c] == 0u);
        }
        // Cold path: ~P(5e-4) per warp-row-triple; exact on arbitrary inputs.
        if (__any_sync(0xffffffffu, emptyAny)) {
            #pragma unroll
            for (int c = 0; c < 3; c++) {
                const int j = lane + 32 * c;
                if (xw[c] == 0u) dl[c] = exact_dl(j, tm[0], tm[1], tm[2]);
                if (yw[c] == 0u) dr[c] = exact_dr(j, tm[0], tm[1], tm[2]);
            }
        }
        #pragma unroll
        for (int c = 0; c < 3; c++) {
            int v = min(dl[c], dr[c]);
            int v2 = v * v;
            rd2own[rr * 3 + c] = v2;
            s_rd2[i * WD + lane + 32 * c] = (unsigned short)v2;
        }
    }

    __syncthreads();   // makes s_rd2 visible block-wide

    // ---- Column scan. di=1 probes come from this thread's own registers where
    // the neighbor row is in-warp-triple (4 of 6 probes); only the triple's
    // outer edges touch smem. Rare tail (bst>4) from di=2 in a lazy branch.
    // Clamped boundary probes only duplicate covered candidates => min safe.
    int best = -1;
    #pragma unroll
    for (int c = 0; c < 3; c++) {
        const int j  = lane + 32 * c;
        const int i0 = wrp * 3;
        int b0 = ((srcbits >> c)       & 1u) ? rd2own[c]     : -1;
        int b1 = ((srcbits >> (3 + c)) & 1u) ? rd2own[3 + c] : -1;
        int b2 = ((srcbits >> (6 + c)) & 1u) ? rd2own[6 + c] : -1;
        // di=1 probes
        int up0 = s_rd2[max(i0 - 1, 0) * WD + j];            // edge: smem
        int dn2 = s_rd2[min(i0 + 3, HD - 1) * WD + j];       // edge: smem
        b0 = min(b0, 1 + min(up0, rd2own[3 + c]));
        b1 = min(b1, 1 + min(rd2own[c], rd2own[6 + c]));
        b2 = min(b2, 1 + min(rd2own[3 + c], dn2));
        // rare tails
        if (b0 > 4) b0 = tail_scan(s_rd2, i0,     j, b0);
        if (b1 > 4) b1 = tail_scan(s_rd2, i0 + 1, j, b1);
        if (b2 > 4) b2 = tail_scan(s_rd2, i0 + 2, j, b2);
        best = max(best, max(b0, max(b1, b2)));
    }

    // ---- Block max-reduction (REDUX within warps)
    best = __reduce_max_sync(0xffffffffu, best);
    if (lane == 0) s_red[wrp] = best;
    __syncthreads();
    if (wrp == 0) {
        int m = __reduce_max_sync(0xffffffffu, s_red[lane]);
        unsigned int t = 0xffffffffu;
        if (lane == 0) {
            // m == -1: empty source -> 0 ; m >= 40000: target empty -> 1e9
            float r;
            if (m < 0)            r = 0.0f;
            else if (m >= 40000)  r = 1e9f;
            else                  r = sqrtf((float)m) * (1.0f / 96.0f);
            g_dir[s * 2 + dir] = r;
            __threadfence();
            t = atomicAdd(&g_count, 1);
        }
        t = __shfl_sync(0xffffffffu, t, 0);
        if (t == (unsigned int)(2 * n - 1)) {        // last block: finish + reset
            __threadfence();
            volatile float* gd = g_dir;
            float v = (lane < 2 * n) ? gd[lane] : 0.0f;
            float h = fmaxf(v, __shfl_xor_sync(0xffffffffu, v, 1));  // pair max
            float acc = (lane & 1) ? 0.0f : h;       // one contribution per sample
            #pragma unroll
            for (int off = 2; off < 32; off <<= 1)
                acc += __shfl_xor_sync(0xffffffffu, acc, off);
            if (lane == 0) {
                out[0] = acc / (float)n;
                g_count = 0;                         // self-reset for next replay
            }
        }
    }
}

extern "C" void kernel_launch(void* const* d_in, const int* in_sizes, int n_in,
                              void* d_out, int out_size) {
    const float* pred = (const float*)d_in[0];
    const float* targ = (const float*)d_in[1];
    float* out = (float*)d_out;
    int n = in_sizes[0] / HW;   // batch size (8)

    dim3 grid(n, 2);
    hausdorff_kernel<<<grid, NT>>>(pred, targ, out, n);
}